// round 10
// baseline (speedup 1.0000x reference)
#include <cuda_runtime.h>
#include <cstdint>

// Problem constants (fixed by setup_inputs)
#define NB    2
#define CIN   32
#define HH    64
#define WW    64
#define LL    (HH * WW)     // 4096
#define OC    32
#define KKK   288           // C * 3 * 3
#define NCHUNK 4                    // K-split per location (contiguous chunks)
#define KC    (KKK / NCHUNK)        // 72 k-rows per chunk
#define NITC  (KC / 4)              // 18 pipeline steps per chunk
#define PF    4                     // loads in flight per lane
#define LOCS_PER_BLOCK 2
#define THREADS (LOCS_PER_BLOCK * NCHUNK * 32)   // 256
#define GRID  (148 * 7)             // persistent: 7 blocks per SM
#define FILT_STRIDE (KKK * OC / 4)  // float4 per location

__global__ __launch_bounds__(THREADS, 7)
void conv_with_filter_kernel(const float* __restrict__ feat,
                             const float4* __restrict__ filt,
                             float* __restrict__ out)
{
    __shared__ float sfeat[LOCS_PER_BLOCK][KKK];           // 2 x 288
    __shared__ float sacc[LOCS_PER_BLOCK][NCHUNK][OC];     // 2 x 4 x 32

    const int tid  = threadIdx.x;
    const int warp = tid >> 5;
    const int lane = tid & 31;

    const int loc   = warp >> 2;        // 0..1
    const int chunk = warp & 3;         // 0..3
    const int g  = lane >> 3;           // k-row within group of 4
    const int o4 = lane & 7;            // float4 column (8 cols = 32 outputs)
    const int kstart = chunk * KC;

    // lane-constant offset into a location's filter block
    const size_t lane_off = (size_t)(kstart + g) * (OC / 4) + o4;

    // ---- prologue: prefetch item 0 ----
    int idx0 = blockIdx.x * LOCS_PER_BLOCK;                // first work item
    const float4* fw = filt + (size_t)(idx0 + loc) * FILT_STRIDE + lane_off;

    float4 buf[PF];
    #pragma unroll
    for (int j = 0; j < PF; j++)
        buf[j] = __ldcs(fw + j * 32);

    // ---- persistent loop over work items ----
    for (; idx0 < NB * LL; idx0 += GRID * LOCS_PER_BLOCK) {
        const int  n     = idx0 >> 12;
        const int  lbase = idx0 & 4095;
        const int  l     = lbase + loc;
        const bool has_next = (idx0 + GRID * LOCS_PER_BLOCK) < NB * LL;
        const float4* fw_next = filt
            + (size_t)(idx0 + GRID * LOCS_PER_BLOCK + loc) * FILT_STRIDE + lane_off;

        // ---- per-warp feature staging (this warp's 72-float slice) ----
        // patch ordering k = c*9 + kh*3 + kw; loads overlap in-flight filter loads
        {
            const int hh = l >> 6;
            const int ww = l & 63;
            #pragma unroll
            for (int j = 0; j < 3; j++) {
                const int k = kstart + j * 32 + lane;      // KC = 72 = 32+32+8
                if (j < 2 || lane < 8) {
                    const int c  = k / 9;
                    const int r  = k % 9;
                    const int hy = hh + (r / 3) - 1;
                    const int wx = ww + (r % 3) - 1;
                    float val = 0.0f;
                    if (hy >= 0 && hy < HH && wx >= 0 && wx < WW)
                        val = __ldg(feat + (((size_t)n * CIN + c) * HH + hy) * WW + wx);
                    sfeat[loc][k] = val;
                }
            }
            __syncwarp();
        }
        const float* s = sfeat[loc] + kstart + g;

        // ---- stream 72 k-rows; tail steps prefetch the NEXT item ----
        float4 acc = make_float4(0.f, 0.f, 0.f, 0.f);

        #pragma unroll
        for (int step = 0; step < NITC; step++) {
            const float4 w4 = buf[step % PF];
            if (step < NITC - PF) {
                buf[step % PF] = __ldcs(fw + (step + PF) * 32);
            } else if (has_next) {
                const int slot = step % PF;                // covers 0..PF-1 once
                buf[slot] = __ldcs(fw_next + slot * 32);
            }
            const float f = s[step * 4];
            acc.x = fmaf(f, w4.x, acc.x);
            acc.y = fmaf(f, w4.y, acc.y);
            acc.z = fmaf(f, w4.z, acc.z);
            acc.w = fmaf(f, w4.w, acc.w);
        }
        fw = fw_next;

        // ---- reduce across the 4 k-row groups within the warp ----
        #pragma unroll
        for (int off = 8; off <= 16; off <<= 1) {
            acc.x += __shfl_xor_sync(0xffffffffu, acc.x, off);
            acc.y += __shfl_xor_sync(0xffffffffu, acc.y, off);
            acc.z += __shfl_xor_sync(0xffffffffu, acc.z, off);
            acc.w += __shfl_xor_sync(0xffffffffu, acc.w, off);
        }

        if (g == 0) {
            float4* sa = reinterpret_cast<float4*>(sacc[loc][chunk]);
            sa[o4] = acc;
        }
        __syncthreads();

        // ---- combine 4 chunk partials, relu, store ----
        // out layout [N, OC, L]
        if (tid < OC * LOCS_PER_BLOCK) {
            const int o  = tid >> 1;        // 0..31
            const int lc = tid & 1;         // 0..1
            float sum = sacc[lc][0][o] + sacc[lc][1][o]
                      + sacc[lc][2][o] + sacc[lc][3][o];
            out[((size_t)n * OC + o) * LL + lbase + lc] = fmaxf(sum, 0.f);
        }
        __syncthreads();   // protect sacc before next iteration's writes
    }
}

extern "C" void kernel_launch(void* const* d_in, const int* in_sizes, int n_in,
                              void* d_out, int out_size)
{
    const float*  feat = (const float*)d_in[0];                // [2,32,64,64]
    const float4* filt = (const float4*)d_in[1];               // [2,4096,288,32]
    float*        out  = (float*)d_out;                        // [2,32,64,64]

    conv_with_filter_kernel<<<GRID, THREADS>>>(feat, filt, out);
}

// round 11
// speedup vs baseline: 1.4187x; 1.4187x over previous
#include <cuda_runtime.h>
#include <cstdint>

// Problem constants (fixed by setup_inputs)
#define NB    2
#define CIN   32
#define HH    64
#define WW    64
#define LL    (HH * WW)     // 4096
#define OC    32
#define KKK   288           // C * 3 * 3
#define NCHUNK 4                    // K-split per location (contiguous chunks)
#define KC    (KKK / NCHUNK)        // 72 k-rows per chunk
#define NITC  (KC / 4)              // 18 pipeline steps per chunk
#define PF    4                     // loads in flight per lane
#define LOCS_PER_BLOCK 2
#define THREADS (LOCS_PER_BLOCK * NCHUNK * 32)   // 256

__global__ __launch_bounds__(THREADS, 7)
void conv_with_filter_kernel(const float* __restrict__ feat,
                             const float4* __restrict__ filt,
                             float* __restrict__ out)
{
    __shared__ float sfeat[LOCS_PER_BLOCK][KKK];           // 2 x 288
    __shared__ float sacc[LOCS_PER_BLOCK][NCHUNK][OC];     // 2 x 4 x 32

    const int tid  = threadIdx.x;
    const int warp = tid >> 5;
    const int lane = tid & 31;

    const int idx0 = blockIdx.x * LOCS_PER_BLOCK;          // first location idx
    const int n    = idx0 >> 12;                           // same n for whole block
    const int lbase = idx0 & 4095;

    const int loc   = warp >> 2;        // 0..1
    const int chunk = warp & 3;         // 0..3
    const int g  = lane >> 3;           // k-row within group of 4
    const int o4 = lane & 7;            // float4 column (8 cols = 32 outputs)

    const int idx    = idx0 + loc;
    const int l      = lbase + loc;
    const int kstart = chunk * KC;

    // ---- issue filter prefetches FIRST (nothing depends on sfeat yet) ----
    const float4* fw = filt + (size_t)idx * (KKK * OC / 4)
                            + (size_t)(kstart + g) * (OC / 4) + o4;
    float4 buf[PF];
    #pragma unroll
    for (int j = 0; j < PF; j++)
        buf[j] = __ldcs(fw + j * 32);

    // ---- per-warp feature staging (only this warp's 72-float slice) ----
    // patch ordering k = c*9 + kh*3 + kw; slice [kstart, kstart+KC)
    {
        const int hh = l >> 6;
        const int ww = l & 63;
        #pragma unroll
        for (int j = 0; j < 3; j++) {
            const int k = kstart + j * 32 + lane;   // KC = 72 = 32+32+8
            if (j < 2 || lane < 8) {
                const int c  = k / 9;
                const int r  = k % 9;
                const int hy = hh + (r / 3) - 1;
                const int wx = ww + (r % 3) - 1;
                float val = 0.0f;
                if (hy >= 0 && hy < HH && wx >= 0 && wx < WW)
                    val = __ldg(feat + (((size_t)n * CIN + c) * HH + hy) * WW + wx);
                sfeat[loc][k] = val;
            }
        }
        __syncwarp();
    }

    const float* s = sfeat[loc] + kstart + g;

    // ---- stream this warp's 72-row contiguous chunk ----
    float4 acc = make_float4(0.f, 0.f, 0.f, 0.f);

    #pragma unroll
    for (int step = 0; step < NITC; step++) {
        const float4 w4 = buf[step % PF];
        if (step < NITC - PF)
            buf[step % PF] = __ldcs(fw + (step + PF) * 32);
        const float f = s[step * 4];
        acc.x = fmaf(f, w4.x, acc.x);
        acc.y = fmaf(f, w4.y, acc.y);
        acc.z = fmaf(f, w4.z, acc.z);
        acc.w = fmaf(f, w4.w, acc.w);
    }

    // ---- reduce across the 4 k-row groups within the warp ----
    #pragma unroll
    for (int off = 8; off <= 16; off <<= 1) {
        acc.x += __shfl_xor_sync(0xffffffffu, acc.x, off);
        acc.y += __shfl_xor_sync(0xffffffffu, acc.y, off);
        acc.z += __shfl_xor_sync(0xffffffffu, acc.z, off);
        acc.w += __shfl_xor_sync(0xffffffffu, acc.w, off);
    }

    if (g == 0) {
        float4* sa = reinterpret_cast<float4*>(sacc[loc][chunk]);
        sa[o4] = acc;
    }
    __syncthreads();

    // ---- combine 4 chunk partials, relu, streaming store ----
    // out layout [N, OC, L]
    if (tid < OC * LOCS_PER_BLOCK) {
        const int o  = tid >> 1;        // 0..31
        const int lc = tid & 1;         // 0..1
        float sum = sacc[lc][0][o] + sacc[lc][1][o] + sacc[lc][2][o] + sacc[lc][3][o];
        __stcs(out + ((size_t)n * OC + o) * LL + lbase + lc, fmaxf(sum, 0.f));
    }
}

extern "C" void kernel_launch(void* const* d_in, const int* in_sizes, int n_in,
                              void* d_out, int out_size)
{
    const float*  feat = (const float*)d_in[0];                // [2,32,64,64]
    const float4* filt = (const float4*)d_in[1];               // [2,4096,288,32]
    float*        out  = (float*)d_out;                        // [2,32,64,64]

    const int blocks = NB * LL / LOCS_PER_BLOCK;               // 4096
    conv_with_filter_kernel<<<blocks, THREADS>>>(feat, filt, out);
}

// round 12
// speedup vs baseline: 1.4254x; 1.0047x over previous
#include <cuda_runtime.h>
#include <cstdint>

// Problem constants (fixed by setup_inputs)
#define NB    2
#define CIN   32
#define HH    64
#define WW    64
#define LL    (HH * WW)     // 4096
#define OC    32
#define KKK   288           // C * 3 * 3
#define NCHUNK 4                    // K-split per location (contiguous chunks)
#define KC    (KKK / NCHUNK)        // 72 k-rows per chunk (= 8 channels x 9)
#define NITC  (KC / 4)              // 18 pipeline steps per chunk
#define PF    4                     // loads in flight per lane
#define LOCS_PER_BLOCK 2
#define THREADS (LOCS_PER_BLOCK * NCHUNK * 32)   // 256

__global__ __launch_bounds__(THREADS, 7)
void conv_with_filter_kernel(const float* __restrict__ feat,
                             const float4* __restrict__ filt,
                             float* __restrict__ out)
{
    __shared__ float sfeat[LOCS_PER_BLOCK][KKK];           // 2 x 288
    __shared__ float sacc[LOCS_PER_BLOCK][NCHUNK][OC];     // 2 x 4 x 32

    const int tid  = threadIdx.x;
    const int warp = tid >> 5;
    const int lane = tid & 31;

    const int idx0 = blockIdx.x * LOCS_PER_BLOCK;          // first location idx
    const int n    = idx0 >> 12;                           // same n for whole block
    const int lbase = idx0 & 4095;

    const int loc   = warp >> 2;        // 0..1
    const int chunk = warp & 3;         // 0..3
    const int g  = lane >> 3;           // k-row within group of 4
    const int o4 = lane & 7;            // float4 column (8 cols = 32 outputs)

    const int idx    = idx0 + loc;
    const int l      = lbase + loc;
    const int kstart = chunk * KC;

    // ---- issue filter prefetches FIRST (nothing depends on sfeat yet) ----
    const float4* fw = filt + (size_t)idx * (KKK * OC / 4)
                            + (size_t)(kstart + g) * (OC / 4) + o4;
    float4 buf[PF];
    #pragma unroll
    for (int j = 0; j < PF; j++)
        buf[j] = __ldcs(fw + j * 32);

    // ---- per-warp feature staging, row-triple coalesced ----
    // This warp's slice covers channels [chunk*8, chunk*8+8). Lane < 24:
    // (c_local = lane/3, kh = lane%3) loads the 3 consecutive wx-1..wx+1
    // floats of one feature row (1 sector instead of 3).
    {
        const int hh = l >> 6;
        const int ww = l & 63;
        if (lane < 24) {
            const int c  = chunk * 8 + lane / 3;
            const int kh = lane % 3;
            const int hy = hh + kh - 1;
            float v0 = 0.f, v1 = 0.f, v2 = 0.f;
            if (hy >= 0 && hy < HH) {
                const float* row = feat + (((size_t)n * CIN + c) * HH + hy) * WW;
                if (ww > 0)      v0 = __ldg(row + ww - 1);
                                 v1 = __ldg(row + ww);
                if (ww + 1 < WW) v2 = __ldg(row + ww + 1);
            }
            float* sp = sfeat[loc] + c * 9 + kh * 3;
            sp[0] = v0; sp[1] = v1; sp[2] = v2;
        }
        __syncwarp();
    }

    const float* s = sfeat[loc] + kstart + g;

    // ---- stream this warp's 72-row contiguous chunk ----
    float4 acc = make_float4(0.f, 0.f, 0.f, 0.f);

    #pragma unroll
    for (int step = 0; step < NITC; step++) {
        const float4 w4 = buf[step % PF];
        if (step < NITC - PF)
            buf[step % PF] = __ldcs(fw + (step + PF) * 32);
        const float f = s[step * 4];
        acc.x = fmaf(f, w4.x, acc.x);
        acc.y = fmaf(f, w4.y, acc.y);
        acc.z = fmaf(f, w4.z, acc.z);
        acc.w = fmaf(f, w4.w, acc.w);
    }

    // ---- reduce across the 4 k-row groups within the warp ----
    #pragma unroll
    for (int off = 8; off <= 16; off <<= 1) {
        acc.x += __shfl_xor_sync(0xffffffffu, acc.x, off);
        acc.y += __shfl_xor_sync(0xffffffffu, acc.y, off);
        acc.z += __shfl_xor_sync(0xffffffffu, acc.z, off);
        acc.w += __shfl_xor_sync(0xffffffffu, acc.w, off);
    }

    if (g == 0) {
        float4* sa = reinterpret_cast<float4*>(sacc[loc][chunk]);
        sa[o4] = acc;
    }
    __syncthreads();

    // ---- combine 4 chunk partials, relu, streaming store ----
    // out layout [N, OC, L]
    if (tid < OC * LOCS_PER_BLOCK) {
        const int o  = tid >> 1;        // 0..31
        const int lc = tid & 1;         // 0..1
        float sum = sacc[lc][0][o] + sacc[lc][1][o] + sacc[lc][2][o] + sacc[lc][3][o];
        __stcs(out + ((size_t)n * OC + o) * LL + lbase + lc, fmaxf(sum, 0.f));
    }
}

extern "C" void kernel_launch(void* const* d_in, const int* in_sizes, int n_in,
                              void* d_out, int out_size)
{
    const float*  feat = (const float*)d_in[0];                // [2,32,64,64]
    const float4* filt = (const float4*)d_in[1];               // [2,4096,288,32]
    float*        out  = (float*)d_out;                        // [2,32,64,64]

    const int blocks = NB * LL / LOCS_PER_BLOCK;               // 4096
    conv_with_filter_kernel<<<blocks, THREADS>>>(feat, filt, out);
}

// round 13
// speedup vs baseline: 1.4264x; 1.0007x over previous
#include <cuda_runtime.h>
#include <cstdint>

// Problem constants (fixed by setup_inputs)
#define NB    2
#define CIN   32
#define HH    64
#define WW    64
#define LL    (HH * WW)     // 4096
#define OC    32
#define KKK   288           // C * 3 * 3
#define NCHUNK 4                    // K-split per location (contiguous chunks)
#define KC    (KKK / NCHUNK)        // 72 k-rows per chunk (= 8 channels x 9)
#define NITC  (KC / 4)              // 18 pipeline steps per chunk
#define PF    4                     // loads in flight per lane
#define LOCS_PER_BLOCK 2
#define THREADS (LOCS_PER_BLOCK * NCHUNK * 32)   // 256

__global__ __launch_bounds__(THREADS, 7)
void conv_with_filter_kernel(const float* __restrict__ feat,
                             const float4* __restrict__ filt,
                             float* __restrict__ out)
{
    __shared__ float sfeat[LOCS_PER_BLOCK][KKK];           // 2 x 288
    __shared__ float sacc[LOCS_PER_BLOCK][NCHUNK][OC];     // 2 x 4 x 32

    const int tid  = threadIdx.x;
    const int warp = tid >> 5;
    const int lane = tid & 31;

    const int idx0 = blockIdx.x * LOCS_PER_BLOCK;          // first location idx
    const int n    = idx0 >> 12;                           // same n for whole block
    const int lbase = idx0 & 4095;

    const int loc   = warp >> 2;        // 0..1
    const int chunk = warp & 3;         // 0..3
    const int g  = lane >> 3;           // k-row within group of 4
    const int o4 = lane & 7;            // float4 column (8 cols = 32 outputs)

    const int idx    = idx0 + loc;
    const int l      = lbase + loc;
    const int kstart = chunk * KC;

    // ---- issue filter prefetches FIRST (nothing depends on sfeat yet) ----
    const float4* fw = filt + (size_t)idx * (KKK * OC / 4)
                            + (size_t)(kstart + g) * (OC / 4) + o4;
    float4 buf[PF];
    #pragma unroll
    for (int j = 0; j < PF; j++)
        buf[j] = __ldcs(fw + j * 32);

    // ---- per-warp feature staging, row-triple coalesced ----
    // This warp's slice covers channels [chunk*8, chunk*8+8). Lane < 24:
    // (c_local = lane/3, kh = lane%3) loads the 3 consecutive wx-1..wx+1
    // floats of one feature row (1 sector instead of 3).
    {
        const int hh = l >> 6;
        const int ww = l & 63;
        if (lane < 24) {
            const int c  = chunk * 8 + lane / 3;
            const int kh = lane % 3;
            const int hy = hh + kh - 1;
            float v0 = 0.f, v1 = 0.f, v2 = 0.f;
            if (hy >= 0 && hy < HH) {
                const float* row = feat + (((size_t)n * CIN + c) * HH + hy) * WW;
                if (ww > 0)      v0 = __ldg(row + ww - 1);
                                 v1 = __ldg(row + ww);
                if (ww + 1 < WW) v2 = __ldg(row + ww + 1);
            }
            float* sp = sfeat[loc] + c * 9 + kh * 3;
            sp[0] = v0; sp[1] = v1; sp[2] = v2;
        }
        __syncwarp();
    }

    const float* s = sfeat[loc] + kstart + g;

    // ---- stream this warp's 72-row contiguous chunk ----
    float4 acc = make_float4(0.f, 0.f, 0.f, 0.f);

    #pragma unroll
    for (int step = 0; step < NITC; step++) {
        const float4 w4 = buf[step % PF];
        if (step < NITC - PF)
            buf[step % PF] = __ldcs(fw + (step + PF) * 32);
        const float f = s[step * 4];
        acc.x = fmaf(f, w4.x, acc.x);
        acc.y = fmaf(f, w4.y, acc.y);
        acc.z = fmaf(f, w4.z, acc.z);
        acc.w = fmaf(f, w4.w, acc.w);
    }

    // ---- reduce across the 4 k-row groups within the warp ----
    #pragma unroll
    for (int off = 8; off <= 16; off <<= 1) {
        acc.x += __shfl_xor_sync(0xffffffffu, acc.x, off);
        acc.y += __shfl_xor_sync(0xffffffffu, acc.y, off);
        acc.z += __shfl_xor_sync(0xffffffffu, acc.z, off);
        acc.w += __shfl_xor_sync(0xffffffffu, acc.w, off);
    }

    if (g == 0) {
        float4* sa = reinterpret_cast<float4*>(sacc[loc][chunk]);
        sa[o4] = acc;
    }
    __syncthreads();

    // ---- combine 4 chunk partials, relu, 8B streaming store ----
    // out layout [N, OC, L]; thread o writes both lc=0,1 as one float2
    if (tid < OC) {
        const int o = tid;
        float s0 = (sacc[0][0][o] + sacc[0][1][o]) + (sacc[0][2][o] + sacc[0][3][o]);
        float s1 = (sacc[1][0][o] + sacc[1][1][o]) + (sacc[1][2][o] + sacc[1][3][o]);
        float2 r = make_float2(fmaxf(s0, 0.f), fmaxf(s1, 0.f));
        __stcs(reinterpret_cast<float2*>(out + ((size_t)n * OC + o) * LL + lbase), r);
    }
}

extern "C" void kernel_launch(void* const* d_in, const int* in_sizes, int n_in,
                              void* d_out, int out_size)
{
    const float*  feat = (const float*)d_in[0];                // [2,32,64,64]
    const float4* filt = (const float4*)d_in[1];               // [2,4096,288,32]
    float*        out  = (float*)d_out;                        // [2,32,64,64]

    const int blocks = NB * LL / LOCS_PER_BLOCK;               // 4096
    conv_with_filter_kernel<<<blocks, THREADS>>>(feat, filt, out);
}